// round 1
// baseline (speedup 1.0000x reference)
#include <cuda_runtime.h>

#define N_REF   50000
#define Q_NUM   4096
#define TN      512                 // refs per smem tile
#define NTILES  98                  // ceil(50000/512)
#define NPAD    (NTILES * TN)       // 50176
#define BLOCK   128
#define QPT     4                   // queries per thread (2 f32x2 pairs)
#define QTILE   (BLOCK * QPT)       // 512
#define QTILES  (Q_NUM / QTILE)     // 8

typedef unsigned long long u64;

// scratch (no allocation allowed in kernel_launch)
__device__ float g_packed[(size_t)NPAD * 16];            // ~3.2 MB
__device__ float g_partial[(size_t)NTILES * Q_NUM * 3];  // ~4.8 MB

// ---------------- f32x2 helpers (Blackwell packed fp32) ----------------
__device__ __forceinline__ u64 fma2(u64 a, u64 b, u64 c) {
    u64 d;
    asm("fma.rn.f32x2 %0, %1, %2, %3;" : "=l"(d) : "l"(a), "l"(b), "l"(c));
    return d;
}
__device__ __forceinline__ u64 add2(u64 a, u64 b) {
    u64 d;
    asm("add.rn.f32x2 %0, %1, %2;" : "=l"(d) : "l"(a), "l"(b));
    return d;
}
__device__ __forceinline__ u64 pack2(float lo, float hi) {
    u64 d;
    asm("mov.b64 %0, {%1, %2};" : "=l"(d) : "f"(lo), "f"(hi));
    return d;
}
__device__ __forceinline__ void unpack2(u64 v, float& lo, float& hi) {
    asm("mov.b64 {%0, %1}, %2;" : "=f"(lo), "=f"(hi) : "l"(v));
}

// ---------------- 1) pack per-reference data, duplicated for f32x2 -----
// layout per n (16 floats / 64B): {r0,r0,r1,r1,r2,r2,r3,r3,r4,r4,rbar,rbar,l0,l0,l1,l1}
// rbar = -k * |r|^2, k = log2(e) / (2*sigma^2).
__global__ void sknn_pack_kernel(const float* __restrict__ Radio,
                                 const float* __restrict__ Loc,
                                 const float* __restrict__ sigma) {
    int n = blockIdx.x * blockDim.x + threadIdx.x;
    if (n >= NPAD) return;
    float s  = sigma[0];
    float k  = 0.5f * 1.4426950408889634f / (s * s);
    float o[16];
    if (n < N_REF) {
        float r2 = 0.0f;
#pragma unroll
        for (int d = 0; d < 5; d++) {
            float r = Radio[n * 5 + d];
            o[2 * d] = r;
            o[2 * d + 1] = r;
            r2 = fmaf(r, r, r2);
        }
        float rbar = -k * r2;
        o[10] = rbar; o[11] = rbar;
        float l0 = Loc[n * 2 + 0], l1 = Loc[n * 2 + 1];
        o[12] = l0; o[13] = l0;
        o[14] = l1; o[15] = l1;
    } else {
        // padding: exp2(-1e30) == 0 -> contributes nothing
#pragma unroll
        for (int i = 0; i < 16; i++) o[i] = 0.0f;
        o[10] = -1e30f; o[11] = -1e30f;
    }
    float4* dst = reinterpret_cast<float4*>(g_packed + (size_t)n * 16);
    const float4* src = reinterpret_cast<const float4*>(o);
    dst[0] = src[0]; dst[1] = src[1]; dst[2] = src[2]; dst[3] = src[3];
}

// ---------------- 2) main: per-tile partial sums ------------------------
__global__ __launch_bounds__(BLOCK)
void sknn_main_kernel(const float* __restrict__ rss,
                      const float* __restrict__ sigma) {
    __shared__ u64 sh[TN * 8];  // 32 KB: one tile of 512 refs

    const int qtile = blockIdx.x;   // 0..7
    const int ntile = blockIdx.y;   // 0..97
    const int t     = threadIdx.x;

    float s  = sigma[0];
    float k2 = 1.4426950408889634f / (s * s);   // 2k

    // 4 queries per thread, packed as 2 f32x2 pairs:
    // pair p holds queries q0 + (2p)*BLOCK and q0 + (2p+1)*BLOCK
    const int q0 = qtile * QTILE + t;
    u64 xs[2][5];
#pragma unroll
    for (int p = 0; p < 2; p++) {
#pragma unroll
        for (int d = 0; d < 5; d++) {
            float a = rss[(q0 + (2 * p + 0) * BLOCK) * 5 + d] * k2;
            float b = rss[(q0 + (2 * p + 1) * BLOCK) * 5 + d] * k2;
            xs[p][d] = pack2(a, b);
        }
    }

    // cooperative smem load of this N-tile: 512 refs * 64B = 2048 float4
    {
        const float4* gsrc = reinterpret_cast<const float4*>(
            g_packed + (size_t)ntile * TN * 16);
        float4* sdst = reinterpret_cast<float4*>(sh);
#pragma unroll
        for (int i = 0; i < (TN * 4) / BLOCK; i++)   // 16 iters
            sdst[t + i * BLOCK] = gsrc[t + i * BLOCK];
    }
    __syncthreads();

    u64 wsum[2] = {0ull, 0ull};   // bit pattern 0 == {0.0f, 0.0f}
    u64 lx[2]   = {0ull, 0ull};
    u64 ly[2]   = {0ull, 0ull};

#pragma unroll 2
    for (int i = 0; i < TN; i++) {
        const ulonglong2* e = reinterpret_cast<const ulonglong2*>(sh + i * 8);
        ulonglong2 v0 = e[0], v1 = e[1], v2 = e[2], v3 = e[3];  // 4x LDS.128 broadcast
        const u64 r0 = v0.x, r1 = v0.y, r2 = v1.x, r3 = v1.y;
        const u64 r4 = v2.x, rb = v2.y, l0 = v3.x, l1 = v3.y;
#pragma unroll
        for (int p = 0; p < 2; p++) {
            u64 acc = fma2(xs[p][0], r0, rb);
            acc = fma2(xs[p][1], r1, acc);
            acc = fma2(xs[p][2], r2, acc);
            acc = fma2(xs[p][3], r3, acc);
            acc = fma2(xs[p][4], r4, acc);
            float alo, ahi;
            unpack2(acc, alo, ahi);
            u64 ev = pack2(exp2f(alo), exp2f(ahi));   // 2x MUFU.EX2
            wsum[p] = add2(wsum[p], ev);
            lx[p]   = fma2(ev, l0, lx[p]);
            ly[p]   = fma2(ev, l1, ly[p]);
        }
    }

    // write partials: [ntile][q][3] = {wsum, lx, ly}
    float* part = g_partial + (size_t)ntile * Q_NUM * 3;
#pragma unroll
    for (int p = 0; p < 2; p++) {
        float w0, w1, x0, x1, y0, y1;
        unpack2(wsum[p], w0, w1);
        unpack2(lx[p],   x0, x1);
        unpack2(ly[p],   y0, y1);
        int qa = q0 + (2 * p + 0) * BLOCK;
        int qb = q0 + (2 * p + 1) * BLOCK;
        part[qa * 3 + 0] = w0; part[qa * 3 + 1] = x0; part[qa * 3 + 2] = y0;
        part[qb * 3 + 0] = w1; part[qb * 3 + 1] = x1; part[qb * 3 + 2] = y1;
    }
}

// ---------------- 3) deterministic reduction + normalize ----------------
__global__ void sknn_reduce_kernel(float* __restrict__ out) {
    int q = blockIdx.x * blockDim.x + threadIdx.x;
    if (q >= Q_NUM) return;
    float w = 0.0f, x = 0.0f, y = 0.0f;
#pragma unroll 7
    for (int c = 0; c < NTILES; c++) {
        const float* p = g_partial + ((size_t)c * Q_NUM + q) * 3;
        w += p[0];
        x += p[1];
        y += p[2];
    }
    float inv = 1.0f / w;
    out[q * 2 + 0] = x * inv;
    out[q * 2 + 1] = y * inv;
}

// ---------------- launch -------------------------------------------------
extern "C" void kernel_launch(void* const* d_in, const int* in_sizes, int n_in,
                              void* d_out, int out_size) {
    (void)in_sizes; (void)n_in; (void)out_size;
    const float* rss   = (const float*)d_in[0];  // [4096, 5]
    const float* Radio = (const float*)d_in[1];  // [50000, 5]
    const float* Loc   = (const float*)d_in[2];  // [50000, 2]
    const float* sigma = (const float*)d_in[3];  // [1]
    float* out = (float*)d_out;                  // [4096, 2]

    sknn_pack_kernel<<<(NPAD + 255) / 256, 256>>>(Radio, Loc, sigma);

    dim3 grid(QTILES, NTILES);
    sknn_main_kernel<<<grid, BLOCK>>>(rss, sigma);

    sknn_reduce_kernel<<<(Q_NUM + 255) / 256, 256>>>(out);
}

// round 2
// speedup vs baseline: 1.2734x; 1.2734x over previous
#include <cuda_runtime.h>

#define N_REF   50000
#define Q_NUM   4096
#define TN      452                 // refs per smem tile
#define NTILES  111                 // 452*111 = 50172 >= 50000
#define NPAD    (NTILES * TN)       // 50172
#define BLOCK   128
#define QPT     4                   // queries per thread (2 f32x2 pairs)
#define QTILE   (BLOCK * QPT)       // 512
#define QTILES  (Q_NUM / QTILE)     // 8  -> 8*111 = 888 blocks = 148 SMs * 6

typedef unsigned long long u64;

// scratch (no allocation allowed in kernel_launch)
__device__ float g_packed[(size_t)NPAD * 16];            // ~3.2 MB
__device__ float g_partial[(size_t)NTILES * Q_NUM * 3];  // ~5.5 MB

// ---------------- f32x2 helpers (Blackwell packed fp32) ----------------
__device__ __forceinline__ u64 fma2(u64 a, u64 b, u64 c) {
    u64 d;
    asm("fma.rn.f32x2 %0, %1, %2, %3;" : "=l"(d) : "l"(a), "l"(b), "l"(c));
    return d;
}
__device__ __forceinline__ u64 add2(u64 a, u64 b) {
    u64 d;
    asm("add.rn.f32x2 %0, %1, %2;" : "=l"(d) : "l"(a), "l"(b));
    return d;
}
__device__ __forceinline__ u64 pack2(float lo, float hi) {
    u64 d;
    asm("mov.b64 %0, {%1, %2};" : "=l"(d) : "f"(lo), "f"(hi));
    return d;
}
__device__ __forceinline__ void unpack2(u64 v, float& lo, float& hi) {
    asm("mov.b64 {%0, %1}, %2;" : "=f"(lo), "=f"(hi) : "l"(v));
}
// raw MUFU.EX2 — exp2 with ~2^-22 rel err, FTZ (exp2(-1e30) -> +0)
__device__ __forceinline__ float ex2(float x) {
    float y;
    asm("ex2.approx.ftz.f32 %0, %1;" : "=f"(y) : "f"(x));
    return y;
}

// ---------------- 1) pack per-reference data, duplicated for f32x2 -----
// layout per n (16 floats / 64B): {r0,r0,r1,r1,r2,r2,r3,r3,r4,r4,rbar,rbar,l0,l0,l1,l1}
// rbar = -k * |r|^2, k = log2(e) / (2*sigma^2).
__global__ void sknn_pack_kernel(const float* __restrict__ Radio,
                                 const float* __restrict__ Loc,
                                 const float* __restrict__ sigma) {
    int n = blockIdx.x * blockDim.x + threadIdx.x;
    if (n >= NPAD) return;
    float s  = sigma[0];
    float k  = 0.5f * 1.4426950408889634f / (s * s);
    float o[16];
    if (n < N_REF) {
        float r2 = 0.0f;
#pragma unroll
        for (int d = 0; d < 5; d++) {
            float r = Radio[n * 5 + d];
            o[2 * d] = r;
            o[2 * d + 1] = r;
            r2 = fmaf(r, r, r2);
        }
        float rbar = -k * r2;
        o[10] = rbar; o[11] = rbar;
        float l0 = Loc[n * 2 + 0], l1 = Loc[n * 2 + 1];
        o[12] = l0; o[13] = l0;
        o[14] = l1; o[15] = l1;
    } else {
        // padding: ex2(-1e30) == +0 -> contributes nothing
#pragma unroll
        for (int i = 0; i < 16; i++) o[i] = 0.0f;
        o[10] = -1e30f; o[11] = -1e30f;
    }
    float4* dst = reinterpret_cast<float4*>(g_packed + (size_t)n * 16);
    const float4* src = reinterpret_cast<const float4*>(o);
    dst[0] = src[0]; dst[1] = src[1]; dst[2] = src[2]; dst[3] = src[3];
}

// ---------------- 2) main: per-tile partial sums ------------------------
__global__ __launch_bounds__(BLOCK, 6)
void sknn_main_kernel(const float* __restrict__ rss,
                      const float* __restrict__ sigma) {
    __shared__ u64 sh[TN * 8];  // 28.9 KB: one tile of 452 refs

    const int qtile = blockIdx.x;   // 0..7
    const int ntile = blockIdx.y;   // 0..110
    const int t     = threadIdx.x;

    float s  = sigma[0];
    float k2 = 1.4426950408889634f / (s * s);   // 2k = log2e / sigma^2

    // 4 queries per thread, packed as 2 f32x2 pairs:
    // pair p holds queries q0 + (2p)*BLOCK and q0 + (2p+1)*BLOCK
    const int q0 = qtile * QTILE + t;
    u64 xs[2][5];
#pragma unroll
    for (int p = 0; p < 2; p++) {
#pragma unroll
        for (int d = 0; d < 5; d++) {
            float a = rss[(q0 + (2 * p + 0) * BLOCK) * 5 + d] * k2;
            float b = rss[(q0 + (2 * p + 1) * BLOCK) * 5 + d] * k2;
            xs[p][d] = pack2(a, b);
        }
    }

    // cooperative smem load of this N-tile: 452 refs * 64B = 1808 float4
    {
        const float4* gsrc = reinterpret_cast<const float4*>(
            g_packed + (size_t)ntile * TN * 16);
        float4* sdst = reinterpret_cast<float4*>(sh);
        for (int i = t; i < TN * 4; i += BLOCK)
            sdst[i] = gsrc[i];
    }
    __syncthreads();

    u64 wsum[2] = {0ull, 0ull};   // bit pattern 0 == {0.0f, 0.0f}
    u64 lx[2]   = {0ull, 0ull};
    u64 ly[2]   = {0ull, 0ull};

#pragma unroll 2
    for (int i = 0; i < TN; i++) {
        const ulonglong2* e = reinterpret_cast<const ulonglong2*>(sh + i * 8);
        ulonglong2 v0 = e[0], v1 = e[1], v2 = e[2], v3 = e[3];  // 4x LDS.128 broadcast
        const u64 r0 = v0.x, r1 = v0.y, r2 = v1.x, r3 = v1.y;
        const u64 r4 = v2.x, rb = v2.y, l0 = v3.x, l1 = v3.y;
#pragma unroll
        for (int p = 0; p < 2; p++) {
            u64 acc = fma2(xs[p][0], r0, rb);
            acc = fma2(xs[p][1], r1, acc);
            acc = fma2(xs[p][2], r2, acc);
            acc = fma2(xs[p][3], r3, acc);
            acc = fma2(xs[p][4], r4, acc);
            float alo, ahi;
            unpack2(acc, alo, ahi);
            u64 ev = pack2(ex2(alo), ex2(ahi));   // 2x raw MUFU.EX2
            wsum[p] = add2(wsum[p], ev);
            lx[p]   = fma2(ev, l0, lx[p]);
            ly[p]   = fma2(ev, l1, ly[p]);
        }
    }

    // write partials: [ntile][q][3] = {wsum, lx, ly}
    float* part = g_partial + (size_t)ntile * Q_NUM * 3;
#pragma unroll
    for (int p = 0; p < 2; p++) {
        float w0, w1, x0, x1, y0, y1;
        unpack2(wsum[p], w0, w1);
        unpack2(lx[p],   x0, x1);
        unpack2(ly[p],   y0, y1);
        int qa = q0 + (2 * p + 0) * BLOCK;
        int qb = q0 + (2 * p + 1) * BLOCK;
        part[qa * 3 + 0] = w0; part[qa * 3 + 1] = x0; part[qa * 3 + 2] = y0;
        part[qb * 3 + 0] = w1; part[qb * 3 + 1] = x1; part[qb * 3 + 2] = y1;
    }
}

// ---------------- 3) deterministic reduction + normalize ----------------
__global__ void sknn_reduce_kernel(float* __restrict__ out) {
    int q = blockIdx.x * blockDim.x + threadIdx.x;
    if (q >= Q_NUM) return;
    float w = 0.0f, x = 0.0f, y = 0.0f;
#pragma unroll 7
    for (int c = 0; c < NTILES; c++) {
        const float* p = g_partial + ((size_t)c * Q_NUM + q) * 3;
        w += p[0];
        x += p[1];
        y += p[2];
    }
    float inv = 1.0f / w;
    out[q * 2 + 0] = x * inv;
    out[q * 2 + 1] = y * inv;
}

// ---------------- launch -------------------------------------------------
extern "C" void kernel_launch(void* const* d_in, const int* in_sizes, int n_in,
                              void* d_out, int out_size) {
    (void)in_sizes; (void)n_in; (void)out_size;
    const float* rss   = (const float*)d_in[0];  // [4096, 5]
    const float* Radio = (const float*)d_in[1];  // [50000, 5]
    const float* Loc   = (const float*)d_in[2];  // [50000, 2]
    const float* sigma = (const float*)d_in[3];  // [1]
    float* out = (float*)d_out;                  // [4096, 2]

    sknn_pack_kernel<<<(NPAD + 255) / 256, 256>>>(Radio, Loc, sigma);

    dim3 grid(QTILES, NTILES);
    sknn_main_kernel<<<grid, BLOCK>>>(rss, sigma);

    sknn_reduce_kernel<<<(Q_NUM + 255) / 256, 256>>>(out);
}

// round 3
// speedup vs baseline: 1.5647x; 1.2287x over previous
#include <cuda_runtime.h>

#define N_REF   50000
#define Q_NUM   4096
#define TN      339                 // refs per smem tile
#define NTILES  148                 // 339*148 = 50172 >= 50000
#define BLOCK   128
#define QPT     8                   // queries per thread (4 f32x2 pairs)
#define NPAIR   (QPT / 2)           // 4
#define QTILE   (BLOCK * QPT)       // 1024
#define QTILES  (Q_NUM / QTILE)     // 4  -> 4*148 = 592 blocks = 148 SMs * 4

typedef unsigned long long u64;

// scratch (no allocation allowed in kernel_launch)
__device__ float g_partial[(size_t)NTILES * Q_NUM * 3];  // ~7.3 MB

// ---------------- f32x2 helpers (Blackwell packed fp32) ----------------
__device__ __forceinline__ u64 fma2(u64 a, u64 b, u64 c) {
    u64 d;
    asm("fma.rn.f32x2 %0, %1, %2, %3;" : "=l"(d) : "l"(a), "l"(b), "l"(c));
    return d;
}
__device__ __forceinline__ u64 add2(u64 a, u64 b) {
    u64 d;
    asm("add.rn.f32x2 %0, %1, %2;" : "=l"(d) : "l"(a), "l"(b));
    return d;
}
__device__ __forceinline__ u64 pack2(float lo, float hi) {
    u64 d;
    asm("mov.b64 %0, {%1, %2};" : "=l"(d) : "f"(lo), "f"(hi));
    return d;
}
__device__ __forceinline__ void unpack2(u64 v, float& lo, float& hi) {
    asm("mov.b64 {%0, %1}, %2;" : "=f"(lo), "=f"(hi) : "l"(v));
}
// raw MUFU.EX2 — exp2 with ~2^-22 rel err, FTZ (ex2(-1e30) -> +0)
__device__ __forceinline__ float ex2(float x) {
    float y;
    asm("ex2.approx.ftz.f32 %0, %1;" : "=f"(y) : "f"(x));
    return y;
}

// ---------------- main: fused pack + per-tile partial sums --------------
// smem layout per ref (16 floats / 64B):
// {r0,r0,r1,r1,r2,r2,r3,r3,r4,r4,rbar,rbar,l0,l0,l1,l1}, rbar = -k*|r|^2,
// k = log2(e)/(2 sigma^2). Inner math: w = exp2(rbar + sum_d xs_d * r_d),
// with xs_d = x_d * 2k. The per-query factor exp2(-k*|x|^2) cancels in the
// row normalization.
__global__ __launch_bounds__(BLOCK, 4)
void sknn_main_kernel(const float* __restrict__ rss,
                      const float* __restrict__ Radio,
                      const float* __restrict__ Loc,
                      const float* __restrict__ sigma) {
    __shared__ u64 sh[TN * 8];  // 21.7 KB

    const int qtile = blockIdx.x;   // 0..3
    const int ntile = blockIdx.y;   // 0..147
    const int t     = threadIdx.x;

    const float s  = sigma[0];
    const float k  = 0.5f * 1.4426950408889634f / (s * s);
    const float k2 = 2.0f * k;

    // ---- pack this block's ref tile directly into smem ----
    for (int i = t; i < TN; i += BLOCK) {
        const int n = ntile * TN + i;
        float o[16];
        if (n < N_REF) {
            float r2 = 0.0f;
#pragma unroll
            for (int d = 0; d < 5; d++) {
                float r = Radio[n * 5 + d];
                o[2 * d] = r;
                o[2 * d + 1] = r;
                r2 = fmaf(r, r, r2);
            }
            float rbar = -k * r2;
            o[10] = rbar; o[11] = rbar;
            float l0 = Loc[n * 2 + 0], l1 = Loc[n * 2 + 1];
            o[12] = l0; o[13] = l0;
            o[14] = l1; o[15] = l1;
        } else {
#pragma unroll
            for (int j = 0; j < 16; j++) o[j] = 0.0f;
            o[10] = -1e30f; o[11] = -1e30f;   // ex2 -> +0: contributes nothing
        }
        float4* dst = reinterpret_cast<float4*>(sh + (size_t)i * 8);
        const float4* src = reinterpret_cast<const float4*>(o);
        dst[0] = src[0]; dst[1] = src[1]; dst[2] = src[2]; dst[3] = src[3];
    }

    // ---- load 8 queries per thread as 4 f32x2 pairs ----
    // pair p holds queries q0 + (2p)*BLOCK and q0 + (2p+1)*BLOCK
    const int q0 = qtile * QTILE + t;
    u64 xs[NPAIR][5];
#pragma unroll
    for (int p = 0; p < NPAIR; p++) {
#pragma unroll
        for (int d = 0; d < 5; d++) {
            float a = rss[(q0 + (2 * p + 0) * BLOCK) * 5 + d] * k2;
            float b = rss[(q0 + (2 * p + 1) * BLOCK) * 5 + d] * k2;
            xs[p][d] = pack2(a, b);
        }
    }
    __syncthreads();

    u64 wsum[NPAIR], lx[NPAIR], ly[NPAIR];
#pragma unroll
    for (int p = 0; p < NPAIR; p++) { wsum[p] = 0ull; lx[p] = 0ull; ly[p] = 0ull; }

#pragma unroll 2
    for (int i = 0; i < TN; i++) {
        const ulonglong2* e = reinterpret_cast<const ulonglong2*>(sh + i * 8);
        ulonglong2 v0 = e[0], v1 = e[1], v2 = e[2], v3 = e[3];  // 4x LDS.128 broadcast
        const u64 r0 = v0.x, r1 = v0.y, r2 = v1.x, r3 = v1.y;
        const u64 r4 = v2.x, rb = v2.y, l0 = v3.x, l1 = v3.y;
#pragma unroll
        for (int p = 0; p < NPAIR; p++) {
            u64 acc = fma2(xs[p][0], r0, rb);
            acc = fma2(xs[p][1], r1, acc);
            acc = fma2(xs[p][2], r2, acc);
            acc = fma2(xs[p][3], r3, acc);
            acc = fma2(xs[p][4], r4, acc);
            float alo, ahi;
            unpack2(acc, alo, ahi);
            u64 ev = pack2(ex2(alo), ex2(ahi));   // 2x raw MUFU.EX2
            wsum[p] = add2(wsum[p], ev);
            lx[p]   = fma2(ev, l0, lx[p]);
            ly[p]   = fma2(ev, l1, ly[p]);
        }
    }

    // write partials: [ntile][q][3] = {wsum, lx, ly}
    float* part = g_partial + (size_t)ntile * Q_NUM * 3;
#pragma unroll
    for (int p = 0; p < NPAIR; p++) {
        float w0, w1, x0, x1, y0, y1;
        unpack2(wsum[p], w0, w1);
        unpack2(lx[p],   x0, x1);
        unpack2(ly[p],   y0, y1);
        int qa = q0 + (2 * p + 0) * BLOCK;
        int qb = q0 + (2 * p + 1) * BLOCK;
        part[qa * 3 + 0] = w0; part[qa * 3 + 1] = x0; part[qa * 3 + 2] = y0;
        part[qb * 3 + 0] = w1; part[qb * 3 + 1] = x1; part[qb * 3 + 2] = y1;
    }
}

// ---------------- deterministic reduction + normalize -------------------
// 4 threads per query, shfl combine within the quad (fixed order -> deterministic)
__global__ void sknn_reduce_kernel(float* __restrict__ out) {
    int gid  = blockIdx.x * blockDim.x + threadIdx.x;  // 0 .. 4*Q_NUM-1
    int q    = gid >> 2;
    int part = gid & 3;
    if (q >= Q_NUM) return;
    float w = 0.0f, x = 0.0f, y = 0.0f;
    for (int c = part; c < NTILES; c += 4) {
        const float* p = g_partial + ((size_t)c * Q_NUM + q) * 3;
        w += p[0];
        x += p[1];
        y += p[2];
    }
    w += __shfl_xor_sync(0xFFFFFFFFu, w, 1);
    x += __shfl_xor_sync(0xFFFFFFFFu, x, 1);
    y += __shfl_xor_sync(0xFFFFFFFFu, y, 1);
    w += __shfl_xor_sync(0xFFFFFFFFu, w, 2);
    x += __shfl_xor_sync(0xFFFFFFFFu, x, 2);
    y += __shfl_xor_sync(0xFFFFFFFFu, y, 2);
    if (part == 0) {
        float inv = 1.0f / w;
        out[q * 2 + 0] = x * inv;
        out[q * 2 + 1] = y * inv;
    }
}

// ---------------- launch -------------------------------------------------
extern "C" void kernel_launch(void* const* d_in, const int* in_sizes, int n_in,
                              void* d_out, int out_size) {
    (void)in_sizes; (void)n_in; (void)out_size;
    const float* rss   = (const float*)d_in[0];  // [4096, 5]
    const float* Radio = (const float*)d_in[1];  // [50000, 5]
    const float* Loc   = (const float*)d_in[2];  // [50000, 2]
    const float* sigma = (const float*)d_in[3];  // [1]
    float* out = (float*)d_out;                  // [4096, 2]

    dim3 grid(QTILES, NTILES);
    sknn_main_kernel<<<grid, BLOCK>>>(rss, Radio, Loc, sigma);

    sknn_reduce_kernel<<<(4 * Q_NUM + 255) / 256, 256>>>(out);
}